// round 1
// baseline (speedup 1.0000x reference)
#include <cuda_runtime.h>
#include <cuda_bf16.h>
#include <math_constants.h>

// Problem constants (fixed shapes from reference)
#define WINS   4096      // 64 * 8 * 8 windows
#define NTOK   49        // 7*7 tokens per window
#define DIM    256
#define HEADS  8
#define DH     32        // DIM / HEADS
#define TTOT   (WINS * NTOK)          // 200704 tokens
#define QKV_E  (3 * DIM)              // 768
#define TABLE  169       // (2*7-1)^2 rel-pos table rows

// Scratch (device globals; allocation inside kernel_launch is forbidden)
__device__ float g_qkv[(size_t)TTOT * QKV_E];   // ~616 MB
__device__ float g_att[(size_t)TTOT * DIM];     // ~205 MB

// ---------------------------------------------------------------------------
// GEMM (NT): C[M,N] = A[M,K] * B[N,K]^T, all row-major. M%128==0, N%64==0, K%16==0.
// 256 threads; 128x64 block tile, 8x4 per-thread micro-tile, BK=16.
// ---------------------------------------------------------------------------
#define BM 128
#define BN 64
#define BK 16
#define TM 8
#define TN 4

__global__ void __launch_bounds__(256) gemm_nt_kernel(
    const float* __restrict__ A, const float* __restrict__ B,
    float* __restrict__ C, int M, int N, int K)
{
    __shared__ float As[BK][BM + 4];
    __shared__ float Bs[BK][BN + 4];

    const int tid = threadIdx.x;
    const int tx = tid & 15;        // 0..15 over N
    const int ty = tid >> 4;        // 0..15 over M
    const int bm = blockIdx.y * BM;
    const int bn = blockIdx.x * BN;

    // Global-load mapping: 4 float4 per A-tile row (BK=16), 4 threads/row
    const int a_row  = tid >> 2;          // 0..63
    const int a_col4 = (tid & 3) << 2;    // 0,4,8,12
    const int b_row  = tid >> 2;          // 0..63
    const int b_col4 = (tid & 3) << 2;

    float acc[TM][TN];
#pragma unroll
    for (int i = 0; i < TM; i++)
#pragma unroll
        for (int j = 0; j < TN; j++) acc[i][j] = 0.f;

    for (int k0 = 0; k0 < K; k0 += BK) {
        // Load A tile (128x16) transposed into smem
#pragma unroll
        for (int r = 0; r < BM; r += 64) {
            float4 va = *(const float4*)&A[(size_t)(bm + a_row + r) * K + k0 + a_col4];
            As[a_col4 + 0][a_row + r] = va.x;
            As[a_col4 + 1][a_row + r] = va.y;
            As[a_col4 + 2][a_row + r] = va.z;
            As[a_col4 + 3][a_row + r] = va.w;
        }
        // Load B tile (64x16) transposed into smem
        {
            float4 vb = *(const float4*)&B[(size_t)(bn + b_row) * K + k0 + b_col4];
            Bs[b_col4 + 0][b_row] = vb.x;
            Bs[b_col4 + 1][b_row] = vb.y;
            Bs[b_col4 + 2][b_row] = vb.z;
            Bs[b_col4 + 3][b_row] = vb.w;
        }
        __syncthreads();

#pragma unroll
        for (int k = 0; k < BK; ++k) {
            float ra[TM], rb[TN];
#pragma unroll
            for (int i = 0; i < TM; i++) ra[i] = As[k][ty * TM + i];
#pragma unroll
            for (int j = 0; j < TN; j++) rb[j] = Bs[k][tx * TN + j];
#pragma unroll
            for (int i = 0; i < TM; i++)
#pragma unroll
                for (int j = 0; j < TN; j++) acc[i][j] = fmaf(ra[i], rb[j], acc[i][j]);
        }
        __syncthreads();
    }

    // Store 8x4 micro-tile (float4 rows)
#pragma unroll
    for (int i = 0; i < TM; i++) {
        float4 v = make_float4(acc[i][0], acc[i][1], acc[i][2], acc[i][3]);
        *(float4*)&C[(size_t)(bm + ty * TM + i) * N + bn + tx * TN] = v;
    }
}

// ---------------------------------------------------------------------------
// Per-(window, head) attention: sim = scale*q@k^T + bias; softmax; out = attn@v
// grid (WINS, HEADS), 128 threads.
// ---------------------------------------------------------------------------
__global__ void __launch_bounds__(128) attn_kernel(
    const float* __restrict__ qkv,       // [TTOT, 768]
    const float* __restrict__ rel_emb,   // [169, 8]
    const int*   __restrict__ rel_idx,   // [49, 49]
    float*       __restrict__ out)       // [TTOT, 256]
{
    __shared__ float qs[NTOK][DH + 1];
    __shared__ float ks[NTOK][DH + 1];
    __shared__ float vs[NTOK][DH + 1];
    __shared__ float sims[NTOK][NTOK];
    __shared__ float bias_tab[TABLE];

    const int win  = blockIdx.x;
    const int head = blockIdx.y;
    const int tid  = threadIdx.x;
    const float scale = 0.17677669529663687f;   // 32^-0.5

    // Load q,k,v for this (window, head)
    const size_t base = (size_t)win * NTOK * QKV_E + head * DH;
    for (int e = tid; e < NTOK * DH; e += 128) {
        int i = e >> 5, c = e & 31;
        const float* p = qkv + base + (size_t)i * QKV_E + c;
        qs[i][c] = p[0];
        ks[i][c] = p[DIM];
        vs[i][c] = p[2 * DIM];
    }
    // Bias table column for this head
    for (int e = tid; e < TABLE; e += 128) bias_tab[e] = rel_emb[e * HEADS + head];
    __syncthreads();

    // sim = scale * q @ k^T + bias
    for (int e = tid; e < NTOK * NTOK; e += 128) {
        int i = e / NTOK, j = e - i * NTOK;
        float s = 0.f;
#pragma unroll
        for (int c = 0; c < DH; c++) s = fmaf(qs[i][c], ks[j][c], s);
        sims[i][j] = s * scale + bias_tab[rel_idx[e]];
    }
    __syncthreads();

    // Row softmax (one thread per row)
    if (tid < NTOK) {
        float m = -CUDART_INF_F;
#pragma unroll 7
        for (int j = 0; j < NTOK; j++) m = fmaxf(m, sims[tid][j]);
        float sum = 0.f;
#pragma unroll 7
        for (int j = 0; j < NTOK; j++) {
            float ev = __expf(sims[tid][j] - m);
            sims[tid][j] = ev;
            sum += ev;
        }
        float inv = 1.f / sum;
#pragma unroll 7
        for (int j = 0; j < NTOK; j++) sims[tid][j] *= inv;
    }
    __syncthreads();

    // out = attn @ v  -> [TTOT, DIM] with head-contiguous layout
    for (int e = tid; e < NTOK * DH; e += 128) {
        int i = e >> 5, c = e & 31;
        float o = 0.f;
#pragma unroll 7
        for (int j = 0; j < NTOK; j++) o = fmaf(sims[i][j], vs[j][c], o);
        out[((size_t)win * NTOK + i) * DIM + head * DH + c] = o;
    }
}

// ---------------------------------------------------------------------------
extern "C" void kernel_launch(void* const* d_in, const int* in_sizes, int n_in,
                              void* d_out, int out_size)
{
    const float* x       = (const float*)d_in[0];   // [64,8,8,7,7,256]
    const float* w_qkv   = (const float*)d_in[1];   // [768,256]
    const float* w_out   = (const float*)d_in[2];   // [256,256]
    const float* rel_emb = (const float*)d_in[3];   // [169,8]
    const int*   rel_idx = (const int*)d_in[4];     // [49,49]
    float* out = (float*)d_out;

    float* qkv;  cudaGetSymbolAddress((void**)&qkv, g_qkv);
    float* att;  cudaGetSymbolAddress((void**)&att, g_att);

    // 1) QKV projection: [200704,768] = x[200704,256] @ w_qkv^T
    gemm_nt_kernel<<<dim3(QKV_E / BN, TTOT / BM), 256>>>(x, w_qkv, qkv, TTOT, QKV_E, DIM);

    // 2) Windowed attention
    attn_kernel<<<dim3(WINS, HEADS), 128>>>(qkv, rel_emb, rel_idx, att);

    // 3) Output projection: [200704,256] = att @ w_out^T
    gemm_nt_kernel<<<dim3(DIM / BN, TTOT / BM), 256>>>(att, w_out, out, TTOT, DIM, DIM);
}

// round 4
// speedup vs baseline: 2.8361x; 2.8361x over previous
#include <cuda_runtime.h>
#include <cstdint>
#include <math_constants.h>

#define WINS   4096
#define NTOK   49
#define DIM    256
#define HEADS  8
#define DH     32
#define TTOT   (WINS * NTOK)      // 200704
#define QKV_E  (3 * DIM)          // 768
#define SCALE  0.17677669529663687f

// ------------------------- scratch (device globals) -------------------------
__device__ float g_qkv[(size_t)TTOT * QKV_E];   // ~616 MB
__device__ float g_att[(size_t)TTOT * DIM];     // ~205 MB
__device__ float g_bias[HEADS * NTOK * NTOK];

// ------------------------------ helpers ------------------------------------
__device__ __forceinline__ float tf32r(float x) {
    float r; asm("cvt.rna.tf32.f32 %0, %1;" : "=f"(r) : "f"(x)); return r;
}
__device__ __forceinline__ unsigned long long pack2(float lo, float hi) {
    unsigned long long r;
    asm("mov.b64 %0, {%1, %2};" : "=l"(r) : "f"(lo), "f"(hi));
    return r;
}
__device__ __forceinline__ void unpack2(unsigned long long v, float& lo, float& hi) {
    asm("mov.b64 {%0, %1}, %2;" : "=f"(lo), "=f"(hi) : "l"(v));
}
#define FMA2(d, a, b, c) \
    asm("fma.rn.f32x2 %0, %1, %2, %3;" : "=l"(d) : "l"(a), "l"(b), "l"(c))
__device__ __forceinline__ float hadd2(unsigned long long v) {
    float lo, hi; unpack2(v, lo, hi); return lo + hi;
}
__device__ __forceinline__ void mma_tf32(float* d, const uint32_t* a, const uint32_t* b) {
    asm volatile(
        "mma.sync.aligned.m16n8k8.row.col.f32.tf32.tf32.f32 "
        "{%0,%1,%2,%3}, {%4,%5,%6,%7}, {%8,%9}, {%0,%1,%2,%3};"
        : "+f"(d[0]), "+f"(d[1]), "+f"(d[2]), "+f"(d[3])
        : "r"(a[0]), "r"(a[1]), "r"(a[2]), "r"(a[3]), "r"(b[0]), "r"(b[1]));
}

// ------------------------------ GEMM (tf32 mma.sync) ------------------------
// C[M,N] = A[M,K] @ B[N,K]^T.  BM=BN=128, BK=32, 256 threads (8 warps, 2x4),
// each warp owns a 64x32 output tile. Double-buffered smem, tf32 rounding
// applied on the global->smem path.
#define BM 128
#define BN 128
#define BK 32
#define KST8 (BK / 8)
#define KSTRIDE 36                       // floats per row ([m][k] padded)
#define A_TILE (BM * KSTRIDE)            // 4608 floats
#define B_TILE (BN * KSTRIDE)
#define SMEM_DYN (2 * (A_TILE + B_TILE) * 4)   // 73728 bytes

__global__ void __launch_bounds__(256, 2) gemm_tf32_kernel(
    const float* __restrict__ A, const float* __restrict__ B,
    float* __restrict__ C, int M, int N, int K)
{
    extern __shared__ float smem[];
    float* sA = smem;                    // [2][BM][KSTRIDE]
    float* sB = smem + 2 * A_TILE;       // [2][BN][KSTRIDE]

    const int tid  = threadIdx.x;
    const int lane = tid & 31;
    const int wid  = tid >> 5;
    const int wm   = wid & 1;            // 0..1  (rows)
    const int wn   = wid >> 1;           // 0..3  (cols)
    const int r    = lane >> 2;          // groupID
    const int c    = lane & 3;           // threadID_in_group
    const int bm   = blockIdx.y * BM;
    const int bn   = blockIdx.x * BN;

    const int KSTEPS = K / BK;

    float acc[4][4][4];
#pragma unroll
    for (int mt = 0; mt < 4; mt++)
#pragma unroll
        for (int nt = 0; nt < 4; nt++)
#pragma unroll
            for (int i = 0; i < 4; i++) acc[mt][nt][i] = 0.f;

    // staging registers: 4 float4 for A, 4 for B
    float4 rgA[4], rgB[4];

    // global load for K-step ks
    auto loadG = [&](int ks) {
        const int k0 = ks * BK;
#pragma unroll
        for (int rr = 0; rr < 4; rr++) {
            int idx = tid + rr * 256;
            int row = idx >> 3, kc = idx & 7;
            rgA[rr] = *(const float4*)&A[(size_t)(bm + row) * K + k0 + kc * 4];
            rgB[rr] = *(const float4*)&B[(size_t)(bn + row) * K + k0 + kc * 4];
        }
    };
    // store staged regs into buffer st (with tf32 rounding)
    auto stsStage = [&](int st) {
        float* dA = sA + st * A_TILE;
        float* dB = sB + st * B_TILE;
#pragma unroll
        for (int rr = 0; rr < 4; rr++) {
            int idx = tid + rr * 256;
            int row = idx >> 3, kc = idx & 7;
            float4 va = rgA[rr];
            va.x = tf32r(va.x); va.y = tf32r(va.y);
            va.z = tf32r(va.z); va.w = tf32r(va.w);
            *(float4*)&dA[row * KSTRIDE + kc * 4] = va;
            float4 vb = rgB[rr];
            vb.x = tf32r(vb.x); vb.y = tf32r(vb.y);
            vb.z = tf32r(vb.z); vb.w = tf32r(vb.w);
            *(float4*)&dB[row * KSTRIDE + kc * 4] = vb;
        }
    };

    loadG(0);
    stsStage(0);
    __syncthreads();

    for (int ks = 0; ks < KSTEPS; ks++) {
        const int cur = ks & 1;
        if (ks + 1 < KSTEPS) loadG(ks + 1);

        const float* Acur = sA + cur * A_TILE + (wm * 64 + r) * KSTRIDE + c;
        const float* Bcur = sB + cur * B_TILE + (wn * 32 + r) * KSTRIDE + c;
#pragma unroll
        for (int k8 = 0; k8 < KST8; k8++) {
            const int kb = k8 * 8;
            uint32_t af[4][4], bf[4][2];
#pragma unroll
            for (int mt = 0; mt < 4; mt++) {
                const float* p = Acur + mt * 16 * KSTRIDE + kb;
                af[mt][0] = __float_as_uint(p[0]);
                af[mt][1] = __float_as_uint(p[8 * KSTRIDE]);
                af[mt][2] = __float_as_uint(p[4]);
                af[mt][3] = __float_as_uint(p[8 * KSTRIDE + 4]);
            }
#pragma unroll
            for (int nt = 0; nt < 4; nt++) {
                const float* p = Bcur + nt * 8 * KSTRIDE + kb;
                bf[nt][0] = __float_as_uint(p[0]);
                bf[nt][1] = __float_as_uint(p[4]);
            }
#pragma unroll
            for (int mt = 0; mt < 4; mt++)
#pragma unroll
                for (int nt = 0; nt < 4; nt++)
                    mma_tf32(acc[mt][nt], af[mt], bf[nt]);
        }

        if (ks + 1 < KSTEPS) {
            __syncthreads();
            stsStage((ks + 1) & 1);
            __syncthreads();
        }
    }

    // epilogue
#pragma unroll
    for (int mt = 0; mt < 4; mt++) {
        const int row = bm + wm * 64 + mt * 16 + r;
#pragma unroll
        for (int nt = 0; nt < 4; nt++) {
            const int col = bn + wn * 32 + nt * 8 + 2 * c;
            float2 v0 = make_float2(acc[mt][nt][0], acc[mt][nt][1]);
            float2 v1 = make_float2(acc[mt][nt][2], acc[mt][nt][3]);
            *(float2*)&C[(size_t)row * N + col] = v0;
            *(float2*)&C[(size_t)(row + 8) * N + col] = v1;
        }
    }
}

// --------------------------- attention (fp32) -------------------------------
// One block = one (window, head). Thread i owns query row i; k/v reads are
// warp-broadcast from SMEM; math uses packed fma.rn.f32x2.
__global__ void __launch_bounds__(64) attn_kernel(
    const float* __restrict__ qkv, const float* __restrict__ biasmat,
    float* __restrict__ out)
{
    __shared__ float ks[NTOK][DH];
    __shared__ float vs[NTOK][DH];
    __shared__ float sims[NTOK][51];

    const int win = blockIdx.x, head = blockIdx.y, tid = threadIdx.x;
    const size_t wbase = (size_t)win * NTOK * QKV_E + head * DH;

    // bias pre-staged into sims
    for (int e = tid; e < NTOK * NTOK; e += 64) {
        int i = e / NTOK, j = e - i * NTOK;
        sims[i][j] = biasmat[head * (NTOK * NTOK) + e];
    }
    // k, v tiles
    for (int u = tid; u < NTOK * 8; u += 64) {
        int j = u >> 3, c4 = u & 7;
        const float* p = qkv + wbase + (size_t)j * QKV_E;
        *(float4*)&ks[j][c4 * 4] = *(const float4*)(p + DIM + c4 * 4);
        *(float4*)&vs[j][c4 * 4] = *(const float4*)(p + 2 * DIM + c4 * 4);
    }
    // q row in registers, scale folded in
    unsigned long long q2[16];
    const int i = tid;
    if (i < NTOK) {
        const float* qp = qkv + wbase + (size_t)i * QKV_E;
#pragma unroll
        for (int c4 = 0; c4 < 8; c4++) {
            float4 v = *(const float4*)(qp + c4 * 4);
            q2[2 * c4]     = pack2(v.x * SCALE, v.y * SCALE);
            q2[2 * c4 + 1] = pack2(v.z * SCALE, v.w * SCALE);
        }
    }
    __syncthreads();

    if (i < NTOK) {
        float m = -CUDART_INF_F;
        for (int j = 0; j < NTOK; j++) {
            unsigned long long a0 = 0ull, a1 = 0ull;
            const unsigned long long* kr = (const unsigned long long*)ks[j];
#pragma unroll
            for (int cc = 0; cc < 16; cc += 2) {
                FMA2(a0, q2[cc],     kr[cc],     a0);
                FMA2(a1, q2[cc + 1], kr[cc + 1], a1);
            }
            float s = hadd2(a0) + hadd2(a1) + sims[i][j];
            sims[i][j] = s;
            m = fmaxf(m, s);
        }
        float sum = 0.f;
        for (int j = 0; j < NTOK; j++) {
            float e = __expf(sims[i][j] - m);
            sims[i][j] = e; sum += e;
        }
        float inv = 1.f / sum;

        unsigned long long o2[16];
#pragma unroll
        for (int cc = 0; cc < 16; cc++) o2[cc] = 0ull;
        for (int j = 0; j < NTOK; j++) {
            float p = sims[i][j];
            unsigned long long pp = pack2(p, p);
            const unsigned long long* vr = (const unsigned long long*)vs[j];
#pragma unroll
            for (int cc = 0; cc < 16; cc++) FMA2(o2[cc], pp, vr[cc], o2[cc]);
        }
        float* orow = out + ((size_t)win * NTOK + i) * DIM + head * DH;
#pragma unroll
        for (int cc = 0; cc < 16; cc += 2) {
            float a, b, x, y;
            unpack2(o2[cc], a, b); unpack2(o2[cc + 1], x, y);
            float4 v = make_float4(a * inv, b * inv, x * inv, y * inv);
            *(float4*)(orow + cc * 2) = v;
        }
    }
}

// ------------------------------ bias expand ---------------------------------
__global__ void bias_expand_kernel(const float* __restrict__ rel_emb,
                                   const int* __restrict__ rel_idx,
                                   float* __restrict__ biasmat)
{
    int e = blockIdx.x * 256 + threadIdx.x;
    if (e < HEADS * NTOK * NTOK) {
        int h = e / (NTOK * NTOK);
        int t = e - h * (NTOK * NTOK);
        biasmat[e] = rel_emb[rel_idx[t] * HEADS + h];
    }
}

// ----------------------------------------------------------------------------
extern "C" void kernel_launch(void* const* d_in, const int* in_sizes, int n_in,
                              void* d_out, int out_size)
{
    const float* x       = (const float*)d_in[0];
    const float* w_qkv   = (const float*)d_in[1];
    const float* w_out   = (const float*)d_in[2];
    const float* rel_emb = (const float*)d_in[3];
    const int*   rel_idx = (const int*)d_in[4];
    float* out = (float*)d_out;

    float *qkv, *att, *bias;
    cudaGetSymbolAddress((void**)&qkv,  g_qkv);
    cudaGetSymbolAddress((void**)&att,  g_att);
    cudaGetSymbolAddress((void**)&bias, g_bias);

    cudaFuncSetAttribute(gemm_tf32_kernel,
                         cudaFuncAttributeMaxDynamicSharedMemorySize, SMEM_DYN);

    bias_expand_kernel<<<(HEADS * NTOK * NTOK + 255) / 256, 256>>>(rel_emb, rel_idx, bias);

    // 1) qkv = x @ w_qkv^T   (tf32 tensor cores via mma.sync)
    gemm_tf32_kernel<<<dim3(QKV_E / BN, TTOT / BM), 256, SMEM_DYN>>>(
        x, w_qkv, qkv, TTOT, QKV_E, DIM);

    // 2) windowed attention
    attn_kernel<<<dim3(WINS, HEADS), 64>>>(qkv, bias, att);

    // 3) out = att @ w_out^T
    gemm_tf32_kernel<<<dim3(DIM / BN, TTOT / BM), 256, SMEM_DYN>>>(
        att, w_out, out, TTOT, DIM, DIM);
}